// round 7
// baseline (speedup 1.0000x reference)
#include <cuda_runtime.h>
#include <cuda_bf16.h>
#include <cstdint>

#define SEQ   4096
#define HD    2048
#define NE    64
#define BATCH 2
#define NTOK  (BATCH*SEQ)
#define SW    1024
#define GATE_BLOCKS 128   // 8192 tokens / 64 per tile
#define RSH   0.02209708691207961f   // 2048^-0.5

// scratch (no cudaMalloc allowed)
__device__ int g_gid[NTOK];

__device__ __forceinline__ bool is_vis(int m) { return (unsigned)(m - 1) <= 1u; }

// packed f32x2 FMA: d = a*b + d  (two independent fp32 lanes)
#define FMA2(d, a, b) asm("fma.rn.f32x2 %0, %1, %2, %3;" \
                          : "=l"(d) : "l"(a), "l"(b), "l"(d))

__device__ __forceinline__ float f2lo(unsigned long long v) {
    return __uint_as_float((unsigned)(v & 0xffffffffu));
}
__device__ __forceinline__ float f2hi(unsigned long long v) {
    return __uint_as_float((unsigned)(v >> 32));
}

// ---------------------------------------------------------------------------
// Kernel 1: vision group-id scan per batch row (2 blocks, trivial)
// ---------------------------------------------------------------------------
__global__ __launch_bounds__(256) void prep_kernel(const int* __restrict__ mm)
{
    int bid = blockIdx.x, tid = threadIdx.x;
    __shared__ int tsum[256];
    __shared__ int toff[256];
    const int* row = mm + bid * SEQ;
    int base = tid * 16;
    int prev = (base == 0) ? 0 : (int)is_vis(row[base - 1]);
    int cnt = 0;
    #pragma unroll
    for (int i = 0; i < 16; i++) {
        int v = (int)is_vis(row[base + i]);
        cnt += (v & (prev ^ 1));
        prev = v;
    }
    tsum[tid] = cnt;
    __syncthreads();
    if (tid == 0) {
        int a = 0;
        for (int i = 0; i < 256; i++) { toff[i] = a; a += tsum[i]; }
    }
    __syncthreads();
    int run = toff[tid];
    prev = (base == 0) ? 0 : (int)is_vis(row[base - 1]);
    #pragma unroll
    for (int i = 0; i < 16; i++) {
        int v = (int)is_vis(row[base + i]);
        run += (v & (prev ^ 1));
        prev = v;
        g_gid[bid * SEQ + base + i] = v ? (run - 1) : -1;
    }
}

// ---------------------------------------------------------------------------
// Kernel 2 (fused): blocks [0,128)  -> gate GEMM (FFMA2) + top-4
//                   blocks [128,..) -> mask rows (DRAM-store-bound)
// ---------------------------------------------------------------------------
__global__ __launch_bounds__(256) void fused_kernel(const float* __restrict__ x,
                                                    const int* __restrict__ packed,
                                                    const float* __restrict__ scale,
                                                    const float* __restrict__ w,
                                                    float* __restrict__ out)
{
    const int bid = blockIdx.x, tid = threadIdx.x;
    const float NEGF = __int_as_float(0xFF7FFFFF);  // -FLT_MAX = finfo(f32).min

    if (bid < GATE_BLOCKS) {
        // ========= gate: 64 tokens x 64 experts, K=2048, f32x2 packed FMA =========
        // smem: A2 (dup'd tokens) float2[32][64] = 16KB  at sh[0..4096)
        //       Bs  float[32][64]               =  8KB  at sh[4096..6144)
        //       reused after compute as L[64][66] logits = 4224 floats
        __shared__ float sh[6144];
        __shared__ float ssq_s[256];
        __shared__ float invs[64];
        float2* A2 = (float2*)sh;               // [k][64] token pairs (a,a)
        float*  Bs = sh + 4096;                 // [k][64]

        const int m0 = bid * 64;
        const int tx = tid & 15;                // expert group: experts tx*4..+3
        const int ty = tid >> 4;                // token group:  tokens ty*4..+3
        const int lt = tid >> 2;                // 0..63 row for staging loads
        const int lc = tid & 3;                 // k-chunk (8 floats)

        unsigned long long acc[4][2];           // [token][expert-pair]
        #pragma unroll
        for (int i = 0; i < 4; i++) { acc[i][0] = 0ull; acc[i][1] = 0ull; }

        const float4* xrow = (const float4*)(x + (size_t)(m0 + lt) * HD);
        const float4* wrow = (const float4*)(w + (size_t)lt * HD);
        float ssq = 0.f;

        for (int k0 = 0; k0 < HD; k0 += 32) {
            int kq = (k0 + lc * 8) >> 2;        // float4 index
            float4 a0 = xrow[kq],     a1 = xrow[kq + 1];
            float4 b0 = wrow[kq],     b1 = wrow[kq + 1];
            float4 s0 = ((const float4*)scale)[kq];
            float4 s1 = ((const float4*)scale)[kq + 1];
            ssq += a0.x*a0.x + a0.y*a0.y + a0.z*a0.z + a0.w*a0.w
                 + a1.x*a1.x + a1.y*a1.y + a1.z*a1.z + a1.w*a1.w;
            __syncthreads();                    // prev-iter reads done
            int kk = lc * 8;
            A2[(kk + 0) * 64 + lt] = make_float2(a0.x, a0.x);
            A2[(kk + 1) * 64 + lt] = make_float2(a0.y, a0.y);
            A2[(kk + 2) * 64 + lt] = make_float2(a0.z, a0.z);
            A2[(kk + 3) * 64 + lt] = make_float2(a0.w, a0.w);
            A2[(kk + 4) * 64 + lt] = make_float2(a1.x, a1.x);
            A2[(kk + 5) * 64 + lt] = make_float2(a1.y, a1.y);
            A2[(kk + 6) * 64 + lt] = make_float2(a1.z, a1.z);
            A2[(kk + 7) * 64 + lt] = make_float2(a1.w, a1.w);
            Bs[(kk + 0) * 64 + lt] = b0.x * s0.x * RSH;
            Bs[(kk + 1) * 64 + lt] = b0.y * s0.y * RSH;
            Bs[(kk + 2) * 64 + lt] = b0.z * s0.z * RSH;
            Bs[(kk + 3) * 64 + lt] = b0.w * s0.w * RSH;
            Bs[(kk + 4) * 64 + lt] = b1.x * s1.x * RSH;
            Bs[(kk + 5) * 64 + lt] = b1.y * s1.y * RSH;
            Bs[(kk + 6) * 64 + lt] = b1.z * s1.z * RSH;
            Bs[(kk + 7) * 64 + lt] = b1.w * s1.w * RSH;
            __syncthreads();
            #pragma unroll
            for (int k = 0; k < 32; k++) {
                // a: 4 tokens, each pre-duplicated as (a,a)
                ulonglong2 aA = *(const ulonglong2*)&A2[k * 64 + ty * 4];      // tok 0,1
                ulonglong2 aB = *(const ulonglong2*)&A2[k * 64 + ty * 4 + 2];  // tok 2,3
                // b: 4 experts as 2 natural pairs
                float4 bv = *(const float4*)&Bs[k * 64 + tx * 4];
                unsigned long long b01, b23;
                asm("mov.b64 %0, {%1, %2};" : "=l"(b01) : "f"(bv.x), "f"(bv.y));
                asm("mov.b64 %0, {%1, %2};" : "=l"(b23) : "f"(bv.z), "f"(bv.w));
                FMA2(acc[0][0], aA.x, b01);  FMA2(acc[0][1], aA.x, b23);
                FMA2(acc[1][0], aA.y, b01);  FMA2(acc[1][1], aA.y, b23);
                FMA2(acc[2][0], aB.x, b01);  FMA2(acc[2][1], aB.x, b23);
                FMA2(acc[3][0], aB.y, b01);  FMA2(acc[3][1], aB.y, b23);
            }
        }
        __syncthreads();                        // done reading A2/Bs, reuse as L[64][66]
        #pragma unroll
        for (int i = 0; i < 4; i++) {
            int t = ty * 4 + i;
            *(float2*)&sh[t * 66 + tx * 4 + 0] = make_float2(f2lo(acc[i][0]), f2hi(acc[i][0]));
            *(float2*)&sh[t * 66 + tx * 4 + 2] = make_float2(f2lo(acc[i][1]), f2hi(acc[i][1]));
        }
        ssq_s[tid] = ssq;
        __syncthreads();
        if (tid < 64) {
            float t = ssq_s[tid * 4] + ssq_s[tid * 4 + 1]
                    + ssq_s[tid * 4 + 2] + ssq_s[tid * 4 + 3];
            invs[tid] = rsqrtf(t * (1.0f / HD) + 1e-6f);
        }
        __syncthreads();

        // top-4 over raw sums s (inv_t > 0 preserves order); weights use l = inv*s
        float* wout = out + (size_t)67108864;   // 2*2^25
        float* iout = out + (size_t)67141632;
        int wi = tid >> 5, lane = tid & 31;
        const float NINF = __int_as_float(0xFF800000);
        for (int r = 0; r < 8; r++) {
            int t = wi * 8 + r;
            float v0 = sh[t * 66 + lane];
            float v1 = sh[t * 66 + 32 + lane];
            float wsel[4]; int isel[4];
            #pragma unroll
            for (int k = 0; k < 4; k++) {
                float bv; int bi;
                if (v0 >= v1) { bv = v0; bi = lane; } else { bv = v1; bi = lane + 32; }
                #pragma unroll
                for (int off = 16; off; off >>= 1) {
                    float ov = __shfl_xor_sync(0xFFFFFFFFu, bv, off);
                    int   oi = __shfl_xor_sync(0xFFFFFFFFu, bi, off);
                    if (ov > bv || (ov == bv && oi < bi)) { bv = ov; bi = oi; }
                }
                wsel[k] = bv; isel[k] = bi;
                if (bi == lane) v0 = NINF;
                else if (bi == lane + 32) v1 = NINF;
            }
            if (lane == 0) {
                float inv = invs[t];
                float m = wsel[0];
                float e0 = 1.0f;                         // exp(inv*(m-m))
                float e1 = __expf(inv * (wsel[1] - m));
                float e2 = __expf(inv * (wsel[2] - m));
                float e3 = __expf(inv * (wsel[3] - m));
                float rs = 1.0f / (e0 + e1 + e2 + e3);
                size_t ob = (size_t)(m0 + t) * 4;
                wout[ob + 0] = e0 * rs;  iout[ob + 0] = (float)isel[0];
                wout[ob + 1] = e1 * rs;  iout[ob + 1] = (float)isel[1];
                wout[ob + 2] = e2 * rs;  iout[ob + 2] = (float)isel[2];
                wout[ob + 3] = e3 * rs;  iout[ob + 3] = (float)isel[3];
            }
        }
    } else {
        // ================= mask: one (b, q) row, write 2x 4096 floats =================
        int id = bid - GATE_BLOCKS;
        int b = id >> 12, q = id & 4095;
        const int* pr = packed + b * SEQ;
        const int* gr = g_gid + b * SEQ;
        int pq = pr[q];
        int gq = gr[q];
        bool pqv = (pq > 0);
        float* fo = out + (((size_t)b) << 24) + (((size_t)q) << 12);
        float* so = fo + ((size_t)1 << 25);

        #pragma unroll
        for (int i = 0; i < 4; i++) {
            int idx = tid + i * 256;
            int kv = idx * 4;
            int4 pk = ((const int4*)pr)[idx];
            int4 gk = ((const int4*)gr)[idx];
            float4 f, s;
            {
                bool sd = (pq == pk.x) & pqv;
                bool fl = sd & (kv <= q);
                bool sb = (fl & ((q - kv) < SW)) | ((gq == gk.x) & (gq >= 0) & sd);
                f.x = fl ? 0.f : NEGF;  s.x = sb ? 0.f : NEGF;
            }
            {
                bool sd = (pq == pk.y) & pqv;
                bool fl = sd & (kv + 1 <= q);
                bool sb = (fl & ((q - kv - 1) < SW)) | ((gq == gk.y) & (gq >= 0) & sd);
                f.y = fl ? 0.f : NEGF;  s.y = sb ? 0.f : NEGF;
            }
            {
                bool sd = (pq == pk.z) & pqv;
                bool fl = sd & (kv + 2 <= q);
                bool sb = (fl & ((q - kv - 2) < SW)) | ((gq == gk.z) & (gq >= 0) & sd);
                f.z = fl ? 0.f : NEGF;  s.z = sb ? 0.f : NEGF;
            }
            {
                bool sd = (pq == pk.w) & pqv;
                bool fl = sd & (kv + 3 <= q);
                bool sb = (fl & ((q - kv - 3) < SW)) | ((gq == gk.w) & (gq >= 0) & sd);
                f.w = fl ? 0.f : NEGF;  s.w = sb ? 0.f : NEGF;
            }
            ((float4*)fo)[idx] = f;
            ((float4*)so)[idx] = s;
        }
    }
}

// ---------------------------------------------------------------------------
// inputs: x, packed_seq_ids, mm_token_type_ids, scale, proj_w
// output (float32): full_mask[2*4096*4096] | sliding_mask[2*4096*4096]
//                   | weights[8192*4] | indices[8192*4]
// ---------------------------------------------------------------------------
extern "C" void kernel_launch(void* const* d_in, const int* in_sizes, int n_in,
                              void* d_out, int out_size)
{
    const float* x      = (const float*)d_in[0];
    const int*   packed = (const int*)  d_in[1];
    const int*   mm     = (const int*)  d_in[2];
    const float* scale  = (const float*)d_in[3];
    const float* projw  = (const float*)d_in[4];
    float* out = (float*)d_out;

    prep_kernel<<<BATCH, 256>>>(mm);
    fused_kernel<<<GATE_BLOCKS + NTOK, 256>>>(x, packed, scale, projw, out);
}

// round 8
// speedup vs baseline: 2.2358x; 2.2358x over previous
#include <cuda_runtime.h>
#include <cuda_bf16.h>
#include <cstdint>

#define SEQ   4096
#define HD    2048
#define NE    64
#define BATCH 2
#define NTOK  (BATCH*SEQ)
#define SW    1024
#define KSPLIT 4
#define KSEG   (HD/KSPLIT)          // 512
#define GATE_TILES 128              // 8192 tokens / 64 per tile
#define GATE_BLOCKS (GATE_TILES*KSPLIT)  // 512
#define RSH   0.02209708691207961f  // 2048^-0.5

// scratch (no cudaMalloc allowed)
__device__ int   g_gid[NTOK];
__device__ float g_part[KSPLIT * NTOK * NE];   // 8 MB partial logits
__device__ float g_ssqp[KSPLIT * NTOK];        // partial sum-of-squares

__device__ __forceinline__ bool is_vis(int m) { return (unsigned)(m - 1) <= 1u; }

// ---------------------------------------------------------------------------
// Kernel 1: vision group-id scan per batch row (2 blocks)
// ---------------------------------------------------------------------------
__global__ __launch_bounds__(256) void prep_kernel(const int* __restrict__ mm)
{
    int bid = blockIdx.x, tid = threadIdx.x;
    __shared__ int tsum[256];
    __shared__ int toff[256];
    const int* row = mm + bid * SEQ;
    int base = tid * 16;
    int prev = (base == 0) ? 0 : (int)is_vis(row[base - 1]);
    int cnt = 0;
    #pragma unroll
    for (int i = 0; i < 16; i++) {
        int v = (int)is_vis(row[base + i]);
        cnt += (v & (prev ^ 1));
        prev = v;
    }
    tsum[tid] = cnt;
    __syncthreads();
    if (tid == 0) {
        int a = 0;
        for (int i = 0; i < 256; i++) { toff[i] = a; a += tsum[i]; }
    }
    __syncthreads();
    int run = toff[tid];
    prev = (base == 0) ? 0 : (int)is_vis(row[base - 1]);
    #pragma unroll
    for (int i = 0; i < 16; i++) {
        int v = (int)is_vis(row[base + i]);
        run += (v & (prev ^ 1));
        prev = v;
        g_gid[bid * SEQ + base + i] = v ? (run - 1) : -1;
    }
}

// ---------------------------------------------------------------------------
// Kernel 2 (fused): blocks [0,512)  -> gate split-K GEMM partials (FMA-bound)
//                   blocks [512,..) -> mask rows (DRAM-store-bound)
// ---------------------------------------------------------------------------
__global__ __launch_bounds__(256) void fused_kernel(const float* __restrict__ x,
                                                    const int* __restrict__ packed,
                                                    const float* __restrict__ scale,
                                                    const float* __restrict__ w,
                                                    float* __restrict__ out)
{
    const int bid = blockIdx.x, tid = threadIdx.x;
    const float NEGF = __int_as_float(0xFF7FFFFF);  // -FLT_MAX = finfo(f32).min

    if (bid < GATE_BLOCKS) {
        // ====== gate partial: 64 tokens x 64 experts, K-segment of 512 ======
        __shared__ float sh[4096];            // As[32][64] | Bs[32][64]
        float* As = sh;
        float* Bs = sh + 2048;

        const int tile = bid & (GATE_TILES - 1);
        const int ks   = bid >> 7;            // K-segment id 0..3
        const int m0   = tile * 64;
        const int tx = tid & 15, ty = tid >> 4;
        const int lt = tid >> 2;              // 0..63 row for staging loads
        const int lc = tid & 3;               // k-chunk (8 floats)

        float acc[4][4];
        #pragma unroll
        for (int i = 0; i < 4; i++)
            #pragma unroll
            for (int j = 0; j < 4; j++) acc[i][j] = 0.f;

        const float4* xrow = (const float4*)(x + (size_t)(m0 + lt) * HD + ks * KSEG);
        const float4* wrow = (const float4*)(w + (size_t)lt * HD + ks * KSEG);
        const float4* srow = (const float4*)(scale + ks * KSEG);
        float ssq = 0.f;

        // prefetch iter 0
        int kq = lc * 2;                       // float4 index within segment
        float4 a0 = xrow[kq], a1 = xrow[kq + 1];
        float4 b0 = wrow[kq], b1 = wrow[kq + 1];
        float4 s0 = srow[kq], s1 = srow[kq + 1];

        for (int k0 = 0; k0 < KSEG; k0 += 32) {
            ssq += a0.x*a0.x + a0.y*a0.y + a0.z*a0.z + a0.w*a0.w
                 + a1.x*a1.x + a1.y*a1.y + a1.z*a1.z + a1.w*a1.w;
            __syncthreads();                   // prev-iter smem reads done
            int kk = lc * 8;
            As[(kk + 0) * 64 + lt] = a0.x;
            As[(kk + 1) * 64 + lt] = a0.y;
            As[(kk + 2) * 64 + lt] = a0.z;
            As[(kk + 3) * 64 + lt] = a0.w;
            As[(kk + 4) * 64 + lt] = a1.x;
            As[(kk + 5) * 64 + lt] = a1.y;
            As[(kk + 6) * 64 + lt] = a1.z;
            As[(kk + 7) * 64 + lt] = a1.w;
            Bs[(kk + 0) * 64 + lt] = b0.x * s0.x * RSH;
            Bs[(kk + 1) * 64 + lt] = b0.y * s0.y * RSH;
            Bs[(kk + 2) * 64 + lt] = b0.z * s0.z * RSH;
            Bs[(kk + 3) * 64 + lt] = b0.w * s0.w * RSH;
            Bs[(kk + 4) * 64 + lt] = b1.x * s1.x * RSH;
            Bs[(kk + 5) * 64 + lt] = b1.y * s1.y * RSH;
            Bs[(kk + 6) * 64 + lt] = b1.z * s1.z * RSH;
            Bs[(kk + 7) * 64 + lt] = b1.w * s1.w * RSH;
            __syncthreads();
            // prefetch next iter while MMA runs (hides L2/DRAM latency)
            if (k0 + 32 < KSEG) {
                kq = ((k0 + 32) >> 2) + lc * 2;
                a0 = xrow[kq]; a1 = xrow[kq + 1];
                b0 = wrow[kq]; b1 = wrow[kq + 1];
                s0 = srow[kq]; s1 = srow[kq + 1];
            }
            #pragma unroll
            for (int k = 0; k < 32; k++) {
                float4 av = *(const float4*)&As[k * 64 + ty * 4];
                float4 bv = *(const float4*)&Bs[k * 64 + tx * 4];
                float a4[4] = {av.x, av.y, av.z, av.w};
                float b4[4] = {bv.x, bv.y, bv.z, bv.w};
                #pragma unroll
                for (int i = 0; i < 4; i++)
                    #pragma unroll
                    for (int j = 0; j < 4; j++)
                        acc[i][j] = fmaf(a4[i], b4[j], acc[i][j]);
            }
        }

        // write partial logits [token, expert] for this K-segment
        float* pbase = g_part + (size_t)ks * NTOK * NE;
        #pragma unroll
        for (int i = 0; i < 4; i++) {
            float4 v = make_float4(acc[i][0], acc[i][1], acc[i][2], acc[i][3]);
            *(float4*)&pbase[(size_t)(m0 + ty * 4 + i) * NE + tx * 4] = v;
        }
        // reduce ssq across the 4 threads of each token row (lanes tid&3)
        ssq += __shfl_xor_sync(0xFFFFFFFFu, ssq, 1);
        ssq += __shfl_xor_sync(0xFFFFFFFFu, ssq, 2);
        if (lc == 0) g_ssqp[ks * NTOK + m0 + lt] = ssq;
    } else {
        // ============ mask: one (b, q) row, write 2x 4096 floats ============
        int id = bid - GATE_BLOCKS;
        int b = id >> 12, q = id & 4095;
        const int* pr = packed + b * SEQ;
        const int* gr = g_gid + b * SEQ;
        int pq = pr[q];
        int gq = gr[q];
        bool pqv = (pq > 0);
        float* fo = out + (((size_t)b) << 24) + (((size_t)q) << 12);
        float* so = fo + ((size_t)1 << 25);

        #pragma unroll
        for (int i = 0; i < 4; i++) {
            int idx = tid + i * 256;
            int kv = idx * 4;
            int4 pk = ((const int4*)pr)[idx];
            int4 gk = ((const int4*)gr)[idx];
            float4 f, s;
            {
                bool sd = (pq == pk.x) & pqv;
                bool fl = sd & (kv <= q);
                bool sb = (fl & ((q - kv) < SW)) | ((gq == gk.x) & (gq >= 0) & sd);
                f.x = fl ? 0.f : NEGF;  s.x = sb ? 0.f : NEGF;
            }
            {
                bool sd = (pq == pk.y) & pqv;
                bool fl = sd & (kv + 1 <= q);
                bool sb = (fl & ((q - kv - 1) < SW)) | ((gq == gk.y) & (gq >= 0) & sd);
                f.y = fl ? 0.f : NEGF;  s.y = sb ? 0.f : NEGF;
            }
            {
                bool sd = (pq == pk.z) & pqv;
                bool fl = sd & (kv + 2 <= q);
                bool sb = (fl & ((q - kv - 2) < SW)) | ((gq == gk.z) & (gq >= 0) & sd);
                f.z = fl ? 0.f : NEGF;  s.z = sb ? 0.f : NEGF;
            }
            {
                bool sd = (pq == pk.w) & pqv;
                bool fl = sd & (kv + 3 <= q);
                bool sb = (fl & ((q - kv - 3) < SW)) | ((gq == gk.w) & (gq >= 0) & sd);
                f.w = fl ? 0.f : NEGF;  s.w = sb ? 0.f : NEGF;
            }
            ((float4*)fo)[idx] = f;
            ((float4*)so)[idx] = s;
        }
    }
}

// ---------------------------------------------------------------------------
// Kernel 3: finalize gate — sum K-partials, inv-RMS, top-4, exp-renorm
// one warp per token; grid 1024 x 256
// ---------------------------------------------------------------------------
__global__ __launch_bounds__(256) void finalize_kernel(float* __restrict__ out)
{
    const int tid = threadIdx.x;
    const int wi = tid >> 5, lane = tid & 31;
    const int t = blockIdx.x * 8 + wi;

    float v0 = 0.f, v1 = 0.f, ssq = 0.f;
    #pragma unroll
    for (int s = 0; s < KSPLIT; s++) {
        const float* p = g_part + ((size_t)s * NTOK + t) * NE;
        v0 += p[lane];
        v1 += p[lane + 32];
        ssq += g_ssqp[s * NTOK + t];
    }
    float inv = rsqrtf(ssq * (1.0f / HD) + 1e-6f);

    float* wout = out + (size_t)67108864;   // 2*2^25
    float* iout = out + (size_t)67141632;
    const float NINF = __int_as_float(0xFF800000);
    float wsel[4]; int isel[4];
    #pragma unroll
    for (int k = 0; k < 4; k++) {
        float bv; int bi;
        if (v0 >= v1) { bv = v0; bi = lane; } else { bv = v1; bi = lane + 32; }
        #pragma unroll
        for (int off = 16; off; off >>= 1) {
            float ov = __shfl_xor_sync(0xFFFFFFFFu, bv, off);
            int   oi = __shfl_xor_sync(0xFFFFFFFFu, bi, off);
            if (ov > bv || (ov == bv && oi < bi)) { bv = ov; bi = oi; }
        }
        wsel[k] = bv; isel[k] = bi;
        if (bi == lane) v0 = NINF;
        else if (bi == lane + 32) v1 = NINF;
    }
    if (lane == 0) {
        float m = wsel[0];
        float e0 = 1.0f;
        float e1 = __expf(inv * (wsel[1] - m));
        float e2 = __expf(inv * (wsel[2] - m));
        float e3 = __expf(inv * (wsel[3] - m));
        float rs = 1.0f / (e0 + e1 + e2 + e3);
        size_t ob = (size_t)t * 4;
        wout[ob + 0] = e0 * rs;  iout[ob + 0] = (float)isel[0];
        wout[ob + 1] = e1 * rs;  iout[ob + 1] = (float)isel[1];
        wout[ob + 2] = e2 * rs;  iout[ob + 2] = (float)isel[2];
        wout[ob + 3] = e3 * rs;  iout[ob + 3] = (float)isel[3];
    }
}

// ---------------------------------------------------------------------------
// inputs: x, packed_seq_ids, mm_token_type_ids, scale, proj_w
// output (float32): full_mask[2*4096*4096] | sliding_mask[2*4096*4096]
//                   | weights[8192*4] | indices[8192*4]
// ---------------------------------------------------------------------------
extern "C" void kernel_launch(void* const* d_in, const int* in_sizes, int n_in,
                              void* d_out, int out_size)
{
    const float* x      = (const float*)d_in[0];
    const int*   packed = (const int*)  d_in[1];
    const int*   mm     = (const int*)  d_in[2];
    const float* scale  = (const float*)d_in[3];
    const float* projw  = (const float*)d_in[4];
    float* out = (float*)d_out;

    prep_kernel<<<BATCH, 256>>>(mm);
    fused_kernel<<<GATE_BLOCKS + NTOK, 256>>>(x, packed, scale, projw, out);
    finalize_kernel<<<NTOK / 8, 256>>>(out);
}